// round 3
// baseline (speedup 1.0000x reference)
#include <cuda_runtime.h>
#include <math.h>

// ---------------- problem constants (fixed shapes) ----------------
#define S_TOK 6240
#define DIMM  1536
#define NH    12
#define HD    128
#define CHK   1560          // chunk = 30*52
#define NC    4             // number of chunks
#define LSEL  3120          // top_k(2) * CHK
#define NKT   25            // ceil(3120/128); last tile ragged (48 valid)
#define C1    22            // rope split: 64 - 2*(64/3)
#define C2    21

// ---------------- scratch (device globals: no cudaMalloc allowed) ----------------
__device__ float g_q[(size_t)S_TOK * DIMM];
__device__ float g_k[(size_t)S_TOK * DIMM];
__device__ float g_v[(size_t)S_TOK * DIMM];
__device__ float g_o[(size_t)S_TOK * DIMM];
__device__ float g_phiq[NH * HD];
__device__ float g_phik[NC * NH * HD];
__device__ int   g_idx[NH * 2];

// ======================================================================
// GEMM: C[M x 1536] = A[M x 1536] * B^T (B is [1536 x 1536] row-major) + bias
// 128x128 tile, BK=16, 256 threads, 8x8 per thread.
// ======================================================================
__global__ __launch_bounds__(256) void gemm_bias_kernel(
    const float* __restrict__ A, const float* __restrict__ B,
    const float* __restrict__ bias, float* __restrict__ C, int M)
{
    __shared__ float As[16][132];   // [k][m]
    __shared__ float Bs[16][132];   // [k][n]
    const int bm = blockIdx.y * 128;
    const int bn = blockIdx.x * 128;
    const int tid = threadIdx.x;
    const int tx = tid & 15;        // n dir
    const int ty = tid >> 4;        // m dir
    const int lr = tid >> 2;        // 0..63 load row
    const int lc = (tid & 3) * 4;   // 0,4,8,12 load col
    const bool full = (bm + 128 <= M);

    float acc[8][8];
#pragma unroll
    for (int i = 0; i < 8; i++)
#pragma unroll
        for (int j = 0; j < 8; j++) acc[i][j] = 0.f;

    for (int k0 = 0; k0 < DIMM; k0 += 16) {
#pragma unroll
        for (int h = 0; h < 2; ++h) {
            int r = lr + h * 64;
            int gr = bm + r;
            float4 av = make_float4(0.f, 0.f, 0.f, 0.f);
            if (full || gr < M) av = *(const float4*)(A + (size_t)gr * DIMM + k0 + lc);
            As[lc + 0][r] = av.x; As[lc + 1][r] = av.y;
            As[lc + 2][r] = av.z; As[lc + 3][r] = av.w;
            float4 bv = *(const float4*)(B + (size_t)(bn + r) * DIMM + k0 + lc);
            Bs[lc + 0][r] = bv.x; Bs[lc + 1][r] = bv.y;
            Bs[lc + 2][r] = bv.z; Bs[lc + 3][r] = bv.w;
        }
        __syncthreads();
#pragma unroll
        for (int kk = 0; kk < 16; ++kk) {
            float a[8], b[8];
            float4 t;
            t = *(const float4*)&As[kk][ty * 8];     a[0]=t.x; a[1]=t.y; a[2]=t.z; a[3]=t.w;
            t = *(const float4*)&As[kk][ty * 8 + 4]; a[4]=t.x; a[5]=t.y; a[6]=t.z; a[7]=t.w;
            t = *(const float4*)&Bs[kk][tx * 8];     b[0]=t.x; b[1]=t.y; b[2]=t.z; b[3]=t.w;
            t = *(const float4*)&Bs[kk][tx * 8 + 4]; b[4]=t.x; b[5]=t.y; b[6]=t.z; b[7]=t.w;
#pragma unroll
            for (int i = 0; i < 8; i++)
#pragma unroll
                for (int j = 0; j < 8; j++)
                    acc[i][j] += a[i] * b[j];
        }
        __syncthreads();
    }
#pragma unroll
    for (int i = 0; i < 8; i++) {
        int row = bm + ty * 8 + i;
        if (!full && row >= M) continue;
#pragma unroll
        for (int j = 0; j < 8; j++) {
            int col = bn + tx * 8 + j;
            C[(size_t)row * DIMM + col] = acc[i][j] + bias[col];
        }
    }
}

// ======================================================================
// Fused RMSNorm (over 1536) + 3D RoPE. grid = (S, 2): y=0 -> q, y=1 -> k.
// ======================================================================
__global__ __launch_bounds__(256) void norm_rope_kernel(
    float* __restrict__ q, float* __restrict__ k,
    const float* __restrict__ gq, const float* __restrict__ gk,
    const float* __restrict__ freqs)
{
    const int s = blockIdx.x;
    float* row = (blockIdx.y == 0 ? q : k) + (size_t)s * DIMM;
    const float* g = (blockIdx.y == 0 ? gq : gk);
    const int tid = threadIdx.x;

    float ss = 0.f;
#pragma unroll
    for (int i = 0; i < 6; i++) { float v = row[tid + i * 256]; ss += v * v; }
#pragma unroll
    for (int off = 16; off > 0; off >>= 1) ss += __shfl_xor_sync(0xffffffffu, ss, off);
    __shared__ float warp_s[8];
    __shared__ float total_s;
    if ((tid & 31) == 0) warp_s[tid >> 5] = ss;
    __syncthreads();
    if (tid == 0) {
        float t = 0.f;
#pragma unroll
        for (int i = 0; i < 8; i++) t += warp_s[i];
        total_s = t;
    }
    __syncthreads();
    const float scale = rsqrtf(total_s * (1.0f / DIMM) + 1e-6f);

    const int f  = s / CHK;
    const int rm = s % CHK;
    const int hh = rm / 52;
    const int ww = rm % 52;

    for (int p = tid; p < DIMM / 2; p += 256) {
        int d0 = 2 * p;
        float a = row[d0]     * scale * g[d0];
        float b = row[d0 + 1] * scale * g[d0 + 1];
        int jh = p & 63;   // pair index within head
        int pos = (jh < C1) ? f : ((jh < C1 + C2) ? hh : ww);
        float cv = freqs[(pos * 64 + jh) * 2 + 0];
        float sv = freqs[(pos * 64 + jh) * 2 + 1];
        row[d0]     = a * cv - b * sv;
        row[d0 + 1] = a * sv + b * cv;
    }
}

// ======================================================================
// phi means: blocks 0..47 -> phik[n][h][:], blocks 48..59 -> phiq[h][:]
// ======================================================================
__global__ void phi_kernel(const float* __restrict__ q, const float* __restrict__ k,
                           float* __restrict__ phiq, float* __restrict__ phik)
{
    int d = threadIdx.x;  // 128
    int b = blockIdx.x;
    if (b < NC * NH) {
        int n = b / NH, h = b % NH;
        float sum = 0.f;
        const float* base = k + (size_t)(n * CHK) * DIMM + h * HD + d;
        for (int r = 0; r < CHK; r++) sum += base[(size_t)r * DIMM];
        phik[(n * NH + h) * HD + d] = sum * (1.0f / CHK);
    } else {
        int h = b - NC * NH;
        float sum = 0.f;
        const float* base = q + h * HD + d;
        for (int r = 0; r < S_TOK; r++) sum += base[(size_t)r * DIMM];
        phiq[h * HD + d] = sum * (1.0f / S_TOK);
    }
}

// ======================================================================
// routing: per-head scores over 4 chunks, top-2, sorted ascending
// ======================================================================
__global__ void route_kernel(const float* __restrict__ phiq,
                             const float* __restrict__ phik, int* __restrict__ idx)
{
    int h = blockIdx.x;
    int lane = threadIdx.x;
    float sc[NC];
#pragma unroll
    for (int n = 0; n < NC; n++) {
        float p = 0.f;
        for (int d = lane; d < HD; d += 32)
            p += phiq[h * HD + d] * phik[(n * NH + h) * HD + d];
#pragma unroll
        for (int off = 16; off > 0; off >>= 1) p += __shfl_xor_sync(0xffffffffu, p, off);
        sc[n] = p;
    }
    if (lane == 0) {
        int i0 = 0;
        for (int n = 1; n < NC; n++) if (sc[n] > sc[i0]) i0 = n;
        int i1 = -1;
        for (int n = 0; n < NC; n++) {
            if (n == i0) continue;
            if (i1 < 0 || sc[n] > sc[i1]) i1 = n;
        }
        idx[h * 2 + 0] = min(i0, i1);
        idx[h * 2 + 1] = max(i0, i1);
    }
}

// ======================================================================
// Flash attention: per (q-tile 128, head). Keys gathered from 2 selected
// chunks. smem: Qt[d][r], KP (Kt[d][c] then reused as P[r][c]), Vs[j][d].
// MASKED template param: only the last key tile needs bounds masking.
// ======================================================================
#define SMEM_FLASH (3 * 128 * 132 * 4)

__device__ __forceinline__ void flash_tile_body(
    float* __restrict__ Qt, float* __restrict__ KP, float* __restrict__ Vs,
    const float* __restrict__ k, const float* __restrict__ v,
    int kb, int c0, int c1, int tx, int ty, int d0,
    float (&accO)[8][8], float (&m_i)[8], float (&l_i)[8], bool masked)
{
    const float scl = 0.08838834764831843f;  // 1/sqrt(128)
    __syncthreads();  // protect prev-iter P/V reads
    // load K (transposed) + V
#pragma unroll
    for (int p = 0; p < 8; p++) {
        int c = p * 16 + ty;
        int jg = kb + c;
        float4 kv0 = make_float4(0.f,0.f,0.f,0.f), kv1 = kv0, vv0 = kv0, vv1 = kv0;
        if (!masked || jg < LSEL) {
            int src = (jg < CHK) ? (c0 + jg) : (c1 + jg - CHK);
            const float* kp_ = k + (size_t)src * DIMM + d0;
            kv0 = *(const float4*)kp_;
            kv1 = *(const float4*)(kp_ + 4);
            const float* vp_ = v + (size_t)src * DIMM + d0;
            vv0 = *(const float4*)vp_;
            vv1 = *(const float4*)(vp_ + 4);
        }
        KP[(d0 + 0) * 132 + c] = kv0.x; KP[(d0 + 1) * 132 + c] = kv0.y;
        KP[(d0 + 2) * 132 + c] = kv0.z; KP[(d0 + 3) * 132 + c] = kv0.w;
        KP[(d0 + 4) * 132 + c] = kv1.x; KP[(d0 + 5) * 132 + c] = kv1.y;
        KP[(d0 + 6) * 132 + c] = kv1.z; KP[(d0 + 7) * 132 + c] = kv1.w;
        *(float4*)&Vs[c * 132 + d0]     = vv0;
        *(float4*)&Vs[c * 132 + d0 + 4] = vv1;
    }
    __syncthreads();

    // S = Q K^T
    float s8[8][8];
#pragma unroll
    for (int i = 0; i < 8; i++)
#pragma unroll
        for (int j = 0; j < 8; j++) s8[i][j] = 0.f;
#pragma unroll 8
    for (int kk = 0; kk < 128; kk++) {
        float a[8], b[8];
        float4 tt;
        tt = *(const float4*)&Qt[kk * 132 + ty * 8];     a[0]=tt.x; a[1]=tt.y; a[2]=tt.z; a[3]=tt.w;
        tt = *(const float4*)&Qt[kk * 132 + ty * 8 + 4]; a[4]=tt.x; a[5]=tt.y; a[6]=tt.z; a[7]=tt.w;
        tt = *(const float4*)&KP[kk * 132 + tx * 8];     b[0]=tt.x; b[1]=tt.y; b[2]=tt.z; b[3]=tt.w;
        tt = *(const float4*)&KP[kk * 132 + tx * 8 + 4]; b[4]=tt.x; b[5]=tt.y; b[6]=tt.z; b[7]=tt.w;
#pragma unroll
        for (int i = 0; i < 8; i++)
#pragma unroll
            for (int j = 0; j < 8; j++)
                s8[i][j] += a[i] * b[j];
    }

    // scale + (optional) mask + online softmax
    float mt[8];
#pragma unroll
    for (int i = 0; i < 8; i++) {
        float mx = -1e30f;
#pragma unroll
        for (int j = 0; j < 8; j++) {
            float val = s8[i][j] * scl;
            if (masked && (kb + tx * 8 + j >= LSEL)) val = -1e30f;
            s8[i][j] = val;
            mx = fmaxf(mx, val);
        }
#pragma unroll
        for (int off = 1; off < 16; off <<= 1)
            mx = fmaxf(mx, __shfl_xor_sync(0xffffffffu, mx, off));
        mt[i] = mx;
    }
#pragma unroll
    for (int i = 0; i < 8; i++) {
        float mn = fmaxf(m_i[i], mt[i]);
        float alpha = __expf(m_i[i] - mn);
        m_i[i] = mn;
        float r = 0.f;
#pragma unroll
        for (int j = 0; j < 8; j++) {
            float p_ = __expf(s8[i][j] - mn);
            s8[i][j] = p_;
            r += p_;
        }
#pragma unroll
        for (int off = 1; off < 16; off <<= 1)
            r += __shfl_xor_sync(0xffffffffu, r, off);
        l_i[i] = l_i[i] * alpha + r;
#pragma unroll
        for (int j = 0; j < 8; j++) accO[i][j] *= alpha;
    }

    __syncthreads();  // everyone done reading Kt
    // write P into KP as P[r][c]
#pragma unroll
    for (int i = 0; i < 8; i++) {
#pragma unroll
        for (int j = 0; j < 8; j++)
            KP[(ty * 8 + i) * 132 + tx * 8 + j] = s8[i][j];
    }
    __syncthreads();

    // O += P * V
#pragma unroll 8
    for (int kk = 0; kk < 128; kk++) {
        float a[8], b[8];
#pragma unroll
        for (int i = 0; i < 8; i++) a[i] = KP[(ty * 8 + i) * 132 + kk];
        float4 tt;
        tt = *(const float4*)&Vs[kk * 132 + tx * 8];     b[0]=tt.x; b[1]=tt.y; b[2]=tt.z; b[3]=tt.w;
        tt = *(const float4*)&Vs[kk * 132 + tx * 8 + 4]; b[4]=tt.x; b[5]=tt.y; b[6]=tt.z; b[7]=tt.w;
#pragma unroll
        for (int i = 0; i < 8; i++)
#pragma unroll
            for (int j = 0; j < 8; j++)
                accO[i][j] += a[i] * b[j];
    }
}

__global__ __launch_bounds__(256, 1) void flash_kernel(
    const float* __restrict__ q, const float* __restrict__ k,
    const float* __restrict__ v, const int* __restrict__ idx,
    float* __restrict__ o)
{
    extern __shared__ float sm[];
    float* Qt = sm;                  // [128][132]  (d-major)
    float* KP = sm + 128 * 132;      // Kt[d][c] / P[r][c]
    float* Vs = sm + 2 * 128 * 132;  // [j][d]

    const int h  = blockIdx.y;
    const int q0 = blockIdx.x * 128;
    const int tid = threadIdx.x;
    const int tx = tid & 15;
    const int ty = tid >> 4;
    const int d0 = tx * 8;
    const bool qfull = (q0 + 128 <= S_TOK);

    // load Q tile transposed
#pragma unroll
    for (int p = 0; p < 8; p++) {
        int r = p * 16 + ty;
        int gr = q0 + r;
        float4 v0 = make_float4(0.f,0.f,0.f,0.f), v1 = v0;
        if (qfull || gr < S_TOK) {
            const float* src = q + (size_t)gr * DIMM + h * HD + d0;
            v0 = *(const float4*)src;
            v1 = *(const float4*)(src + 4);
        }
        Qt[(d0 + 0) * 132 + r] = v0.x; Qt[(d0 + 1) * 132 + r] = v0.y;
        Qt[(d0 + 2) * 132 + r] = v0.z; Qt[(d0 + 3) * 132 + r] = v0.w;
        Qt[(d0 + 4) * 132 + r] = v1.x; Qt[(d0 + 5) * 132 + r] = v1.y;
        Qt[(d0 + 6) * 132 + r] = v1.z; Qt[(d0 + 7) * 132 + r] = v1.w;
    }
    const int c0 = idx[h * 2 + 0] * CHK;
    const int c1 = idx[h * 2 + 1] * CHK;
    const float* kh = k + h * HD;
    const float* vh = v + h * HD;

    float accO[8][8];
    float m_i[8], l_i[8];
#pragma unroll
    for (int i = 0; i < 8; i++) {
        m_i[i] = -1e30f; l_i[i] = 0.f;
#pragma unroll
        for (int j = 0; j < 8; j++) accO[i][j] = 0.f;
    }

    for (int t = 0; t < NKT - 1; ++t)
        flash_tile_body(Qt, KP, Vs, kh, vh, t * 128, c0, c1, tx, ty, d0,
                        accO, m_i, l_i, false);
    flash_tile_body(Qt, KP, Vs, kh, vh, (NKT - 1) * 128, c0, c1, tx, ty, d0,
                    accO, m_i, l_i, true);

    // epilogue
#pragma unroll
    for (int i = 0; i < 8; i++) {
        int row = q0 + ty * 8 + i;
        if (!qfull && row >= S_TOK) continue;
        float inv = 1.0f / l_i[i];
        float4 o0, o1;
        o0.x = accO[i][0] * inv; o0.y = accO[i][1] * inv;
        o0.z = accO[i][2] * inv; o0.w = accO[i][3] * inv;
        o1.x = accO[i][4] * inv; o1.y = accO[i][5] * inv;
        o1.z = accO[i][6] * inv; o1.w = accO[i][7] * inv;
        float* dst = o + (size_t)row * DIMM + h * HD + tx * 8;
        *(float4*)dst = o0;
        *(float4*)(dst + 4) = o1;
    }
}

// ======================================================================
extern "C" void kernel_launch(void* const* d_in, const int* in_sizes, int n_in,
                              void* d_out, int out_size)
{
    const float* x     = (const float*)d_in[0];
    const float* freqs = (const float*)d_in[3];
    const float* wq    = (const float*)d_in[4];
    const float* bq    = (const float*)d_in[5];
    const float* wk    = (const float*)d_in[6];
    const float* bk    = (const float*)d_in[7];
    const float* wv    = (const float*)d_in[8];
    const float* bv    = (const float*)d_in[9];
    const float* wo    = (const float*)d_in[10];
    const float* bo    = (const float*)d_in[11];
    const float* gq    = (const float*)d_in[12];
    const float* gk    = (const float*)d_in[13];
    float* out = (float*)d_out;

    float *qb, *kb, *vb, *ob, *phiq, *phik;
    int* idxp;
    cudaGetSymbolAddress((void**)&qb,   g_q);
    cudaGetSymbolAddress((void**)&kb,   g_k);
    cudaGetSymbolAddress((void**)&vb,   g_v);
    cudaGetSymbolAddress((void**)&ob,   g_o);
    cudaGetSymbolAddress((void**)&phiq, g_phiq);
    cudaGetSymbolAddress((void**)&phik, g_phik);
    cudaGetSymbolAddress((void**)&idxp, g_idx);

    dim3 gemm_grid(DIMM / 128, (S_TOK + 127) / 128);
    gemm_bias_kernel<<<gemm_grid, 256>>>(x, wq, bq, qb, S_TOK);
    gemm_bias_kernel<<<gemm_grid, 256>>>(x, wk, bk, kb, S_TOK);
    gemm_bias_kernel<<<gemm_grid, 256>>>(x, wv, bv, vb, S_TOK);

    norm_rope_kernel<<<dim3(S_TOK, 2), 256>>>(qb, kb, gq, gk, freqs);

    phi_kernel<<<NC * NH + NH, 128>>>(qb, kb, phiq, phik);
    route_kernel<<<NH, 32>>>(phiq, phik, idxp);

    cudaFuncSetAttribute(flash_kernel, cudaFuncAttributeMaxDynamicSharedMemorySize, SMEM_FLASH);
    flash_kernel<<<dim3((S_TOK + 127) / 128, NH), 256, SMEM_FLASH>>>(qb, kb, vb, idxp, ob);

    gemm_bias_kernel<<<gemm_grid, 256>>>(ob, wo, bo, out, S_TOK);
}

// round 7
// speedup vs baseline: 1.2437x; 1.2437x over previous
#include <cuda_runtime.h>
#include <cuda_bf16.h>
#include <math.h>
#include <stdint.h>

// ---------------- problem constants (fixed shapes) ----------------
#define S_TOK 6240
#define DIMM  1536
#define NH    12
#define HD    128
#define CHK   1560          // chunk = 30*52
#define NC    4             // number of chunks
#define LSEL  3120          // top_k(2) * CHK
#define NKT   25            // ceil(3120/128); last tile ragged (48 valid)
#define C1    22            // rope split: 64 - 2*(64/3)
#define C2    21

// ---------------- scratch (device globals: no cudaMalloc allowed) ----------------
__device__ float g_q[(size_t)S_TOK * DIMM];
__device__ float g_k[(size_t)S_TOK * DIMM];
__device__ float g_v[(size_t)S_TOK * DIMM];
__device__ float g_o[(size_t)S_TOK * DIMM];
__device__ float g_phiq[NH * HD];
__device__ float g_phik[NC * NH * HD];
__device__ int   g_idx[NH * 2];

// ======================================================================
// warp-mma helpers (base sm_100: ldmatrix + mma.sync, NO tcgen05)
// ======================================================================
__device__ __forceinline__ uint32_t smem_u32(const void* p) {
    uint32_t a;
    asm("{ .reg .u64 t; cvta.to.shared.u64 t, %1; cvt.u32.u64 %0, t; }" : "=r"(a) : "l"(p));
    return a;
}
__device__ __forceinline__ void ldm_x4(uint32_t* r, uint32_t addr) {
    asm volatile("ldmatrix.sync.aligned.m8n8.x4.shared.b16 {%0,%1,%2,%3}, [%4];"
        : "=r"(r[0]), "=r"(r[1]), "=r"(r[2]), "=r"(r[3]) : "r"(addr));
}
__device__ __forceinline__ void ldm_x2(uint32_t* r, uint32_t addr) {
    asm volatile("ldmatrix.sync.aligned.m8n8.x2.shared.b16 {%0,%1}, [%2];"
        : "=r"(r[0]), "=r"(r[1]) : "r"(addr));
}
__device__ __forceinline__ void mma16816(float* c, const uint32_t* a, const uint32_t* b) {
    asm volatile("mma.sync.aligned.m16n8k16.row.col.f32.bf16.bf16.f32 "
        "{%0,%1,%2,%3}, {%4,%5,%6,%7}, {%8,%9}, {%0,%1,%2,%3};"
        : "+f"(c[0]), "+f"(c[1]), "+f"(c[2]), "+f"(c[3])
        : "r"(a[0]), "r"(a[1]), "r"(a[2]), "r"(a[3]), "r"(b[0]), "r"(b[1]));
}

__device__ __forceinline__ uint32_t pack_bf2(__nv_bfloat16 a, __nv_bfloat16 b) {
    return ((uint32_t)__bfloat16_as_ushort(b) << 16) | (uint32_t)__bfloat16_as_ushort(a);
}
// split 8 floats into hi/lo bf16 packs
__device__ __forceinline__ void split8(const float4 f0, const float4 f1,
                                       uint4& hi, uint4& lo) {
    float x[8] = {f0.x, f0.y, f0.z, f0.w, f1.x, f1.y, f1.z, f1.w};
    __nv_bfloat16 h[8], l[8];
#pragma unroll
    for (int i = 0; i < 8; i++) {
        h[i] = __float2bfloat16(x[i]);
        l[i] = __float2bfloat16(x[i] - __bfloat162float(h[i]));
    }
    hi.x = pack_bf2(h[0], h[1]); hi.y = pack_bf2(h[2], h[3]);
    hi.z = pack_bf2(h[4], h[5]); hi.w = pack_bf2(h[6], h[7]);
    lo.x = pack_bf2(l[0], l[1]); lo.y = pack_bf2(l[2], l[3]);
    lo.z = pack_bf2(l[4], l[5]); lo.w = pack_bf2(l[6], l[7]);
}

// ======================================================================
// HMMA GEMM: C[M x 1536] = A[M x 1536] @ W^T + bias  (W row-major [n][k])
// Split-bf16 hi/lo, 3 passes (hh, hl, lh). 128x128 CTA tile, 8 warps
// (2x4), warp tile 64x32, K-chunk 32, double-buffered smem.
// Row stride 40 bf16 (80B) -> conflict-free ldmatrix.
// ======================================================================
#define KC 32
#define NCHUNK (DIMM / KC)          // 48
#define RS 40                       // smem row stride, bf16 units
#define ARR_B (128 * RS * 2)        // 10240 B per array
#define STAGE_B (4 * ARR_B)         // Ahi,Alo,Whi,Wlo
#define MM_SMEM (2 * STAGE_B)       // 81920 B

__global__ __launch_bounds__(256, 1)
void gemm_mma_kernel(const float* __restrict__ A, const float* __restrict__ W,
                     const float* __restrict__ bias, float* __restrict__ C, int M)
{
    extern __shared__ char sm_raw[];
    const uint32_t sb = smem_u32(sm_raw);
    const int tid  = threadIdx.x;
    const int lane = tid & 31;
    const int warp = tid >> 5;
    const int wm = warp >> 2;       // 0..1
    const int wn = warp & 3;        // 0..3
    const int bm = blockIdx.y * 128;
    const int bn = blockIdx.x * 128;
    const bool full = (bm + 128 <= M);

    const int lrow = tid >> 1;          // 0..127
    const int lcb  = (tid & 1) * 16;    // 0 / 16 (col base within chunk)
    const bool arow_ok = full || (bm + lrow < M);
    const int arow_clamped = arow_ok ? (bm + lrow) : 0;   // keep ptr math in-bounds
    const float* arow_p = A + (size_t)arow_clamped * DIMM + lcb;
    const float* wrow_p = W + (size_t)(bn + lrow) * DIMM + lcb;

    float4 pa[4], pw[4];

    float acc[4][4][4];
#pragma unroll
    for (int mi = 0; mi < 4; mi++)
#pragma unroll
        for (int ni = 0; ni < 4; ni++)
#pragma unroll
            for (int e = 0; e < 4; e++) acc[mi][ni][e] = 0.f;

    // ---- prologue: chunk 0 ----
    {
        if (arow_ok) {
            const float4* p = (const float4*)arow_p;
            pa[0] = p[0]; pa[1] = p[1]; pa[2] = p[2]; pa[3] = p[3];
        } else {
            pa[0] = pa[1] = pa[2] = pa[3] = make_float4(0.f, 0.f, 0.f, 0.f);
        }
        const float4* q = (const float4*)wrow_p;
        pw[0] = q[0]; pw[1] = q[1]; pw[2] = q[2]; pw[3] = q[3];

        char* base = sm_raw;
        const uint32_t off = (uint32_t)(lrow * RS + lcb) * 2;
        uint4 hi, lo;
        split8(pa[0], pa[1], hi, lo);
        *(uint4*)(base + off) = hi;  *(uint4*)(base + ARR_B + off) = lo;
        split8(pa[2], pa[3], hi, lo);
        *(uint4*)(base + off + 16) = hi;  *(uint4*)(base + ARR_B + off + 16) = lo;
        split8(pw[0], pw[1], hi, lo);
        *(uint4*)(base + 2 * ARR_B + off) = hi;  *(uint4*)(base + 3 * ARR_B + off) = lo;
        split8(pw[2], pw[3], hi, lo);
        *(uint4*)(base + 2 * ARR_B + off + 16) = hi;  *(uint4*)(base + 3 * ARR_B + off + 16) = lo;
    }
    __syncthreads();

    const uint32_t aoff = (uint32_t)((lane & 15) * RS + ((lane >> 4) << 3)) * 2;
    const uint32_t boff = (uint32_t)((lane & 7) * RS + (((lane >> 3) & 1) << 3)) * 2;

    for (int c = 0; c < NCHUNK; ++c) {
        const int buf = c & 1;
        // prefetch next chunk into registers
        if (c + 1 < NCHUNK) {
            const int k0 = (c + 1) * KC;
            if (arow_ok) {
                const float4* p = (const float4*)(arow_p + k0);
                pa[0] = p[0]; pa[1] = p[1]; pa[2] = p[2]; pa[3] = p[3];
            } else {
                pa[0] = pa[1] = pa[2] = pa[3] = make_float4(0.f, 0.f, 0.f, 0.f);
            }
            const float4* q = (const float4*)(wrow_p + k0);
            pw[0] = q[0]; pw[1] = q[1]; pw[2] = q[2]; pw[3] = q[3];
        }

        // compute current chunk
        const uint32_t st = sb + buf * STAGE_B;
#pragma unroll
        for (int ks = 0; ks < 2; ++ks) {
            uint32_t ahi[4][4], alo[4][4], bhi[4][2], blo[4][2];
            const uint32_t kso = ks * 32;   // 16 bf16 cols = 32 bytes
#pragma unroll
            for (int mi = 0; mi < 4; ++mi) {
                uint32_t r = st + (uint32_t)((wm * 64 + mi * 16) * RS * 2) + aoff + kso;
                ldm_x4(ahi[mi], r);
                ldm_x4(alo[mi], r + ARR_B);
            }
#pragma unroll
            for (int ni = 0; ni < 4; ++ni) {
                uint32_t r = st + 2 * ARR_B + (uint32_t)((wn * 32 + ni * 8) * RS * 2) + boff + kso;
                ldm_x2(bhi[ni], r);
                ldm_x2(blo[ni], r + ARR_B);
            }
#pragma unroll
            for (int mi = 0; mi < 4; ++mi)
#pragma unroll
                for (int ni = 0; ni < 4; ++ni) {
                    mma16816(acc[mi][ni], ahi[mi], bhi[ni]);
                    mma16816(acc[mi][ni], ahi[mi], blo[ni]);
                    mma16816(acc[mi][ni], alo[mi], bhi[ni]);
                }
        }

        // store prefetched chunk into the other buffer
        if (c + 1 < NCHUNK) {
            __syncthreads();   // all warps done reading buf^1 (from iter c-1)
            char* base = sm_raw + (buf ^ 1) * STAGE_B;
            const uint32_t off = (uint32_t)(lrow * RS + lcb) * 2;
            uint4 hi, lo;
            split8(pa[0], pa[1], hi, lo);
            *(uint4*)(base + off) = hi;  *(uint4*)(base + ARR_B + off) = lo;
            split8(pa[2], pa[3], hi, lo);
            *(uint4*)(base + off + 16) = hi;  *(uint4*)(base + ARR_B + off + 16) = lo;
            split8(pw[0], pw[1], hi, lo);
            *(uint4*)(base + 2 * ARR_B + off) = hi;  *(uint4*)(base + 3 * ARR_B + off) = lo;
            split8(pw[2], pw[3], hi, lo);
            *(uint4*)(base + 2 * ARR_B + off + 16) = hi;  *(uint4*)(base + 3 * ARR_B + off + 16) = lo;
            __syncthreads();   // writes visible before next compute
        }
    }

    // ---- epilogue ----
#pragma unroll
    for (int mi = 0; mi < 4; ++mi) {
        const int r0 = bm + wm * 64 + mi * 16 + (lane >> 2);
#pragma unroll
        for (int ni = 0; ni < 4; ++ni) {
            const int c0 = bn + wn * 32 + ni * 8 + (lane & 3) * 2;
            const float b0 = bias[c0], b1 = bias[c0 + 1];
            if (full || r0 < M) {
                float2 v = make_float2(acc[mi][ni][0] + b0, acc[mi][ni][1] + b1);
                *(float2*)(C + (size_t)r0 * DIMM + c0) = v;
            }
            if (full || r0 + 8 < M) {
                float2 v = make_float2(acc[mi][ni][2] + b0, acc[mi][ni][3] + b1);
                *(float2*)(C + (size_t)(r0 + 8) * DIMM + c0) = v;
            }
        }
    }
}

// ======================================================================
// Fused RMSNorm (over 1536) + 3D RoPE. grid = (S, 2): y=0 -> q, y=1 -> k.
// ======================================================================
__global__ __launch_bounds__(256) void norm_rope_kernel(
    float* __restrict__ q, float* __restrict__ k,
    const float* __restrict__ gq, const float* __restrict__ gk,
    const float* __restrict__ freqs)
{
    const int s = blockIdx.x;
    float* row = (blockIdx.y == 0 ? q : k) + (size_t)s * DIMM;
    const float* g = (blockIdx.y == 0 ? gq : gk);
    const int tid = threadIdx.x;

    float ss = 0.f;
#pragma unroll
    for (int i = 0; i < 6; i++) { float v = row[tid + i * 256]; ss += v * v; }
#pragma unroll
    for (int off = 16; off > 0; off >>= 1) ss += __shfl_xor_sync(0xffffffffu, ss, off);
    __shared__ float warp_s[8];
    __shared__ float total_s;
    if ((tid & 31) == 0) warp_s[tid >> 5] = ss;
    __syncthreads();
    if (tid == 0) {
        float t = 0.f;
#pragma unroll
        for (int i = 0; i < 8; i++) t += warp_s[i];
        total_s = t;
    }
    __syncthreads();
    const float scale = rsqrtf(total_s * (1.0f / DIMM) + 1e-6f);

    const int f  = s / CHK;
    const int rm = s % CHK;
    const int hh = rm / 52;
    const int ww = rm % 52;

    for (int p = tid; p < DIMM / 2; p += 256) {
        int d0 = 2 * p;
        float a = row[d0]     * scale * g[d0];
        float b = row[d0 + 1] * scale * g[d0 + 1];
        int jh = p & 63;   // pair index within head
        int pos = (jh < C1) ? f : ((jh < C1 + C2) ? hh : ww);
        float cv = freqs[(pos * 64 + jh) * 2 + 0];
        float sv = freqs[(pos * 64 + jh) * 2 + 1];
        row[d0]     = a * cv - b * sv;
        row[d0 + 1] = a * sv + b * cv;
    }
}

// ======================================================================
// phi means: blocks 0..47 -> phik[n][h][:], blocks 48..59 -> phiq[h][:]
// ======================================================================
__global__ void phi_kernel(const float* __restrict__ q, const float* __restrict__ k,
                           float* __restrict__ phiq, float* __restrict__ phik)
{
    int d = threadIdx.x;  // 128
    int b = blockIdx.x;
    if (b < NC * NH) {
        int n = b / NH, h = b % NH;
        float sum = 0.f;
        const float* base = k + (size_t)(n * CHK) * DIMM + h * HD + d;
        for (int r = 0; r < CHK; r++) sum += base[(size_t)r * DIMM];
        phik[(n * NH + h) * HD + d] = sum * (1.0f / CHK);
    } else {
        int h = b - NC * NH;
        float sum = 0.f;
        const float* base = q + h * HD + d;
        for (int r = 0; r < S_TOK; r++) sum += base[(size_t)r * DIMM];
        phiq[h * HD + d] = sum * (1.0f / S_TOK);
    }
}

// ======================================================================
// routing: per-head scores over 4 chunks, top-2, sorted ascending
// ======================================================================
__global__ void route_kernel(const float* __restrict__ phiq,
                             const float* __restrict__ phik, int* __restrict__ idx)
{
    int h = blockIdx.x;
    int lane = threadIdx.x;
    float sc[NC];
#pragma unroll
    for (int n = 0; n < NC; n++) {
        float p = 0.f;
        for (int d = lane; d < HD; d += 32)
            p += phiq[h * HD + d] * phik[(n * NH + h) * HD + d];
#pragma unroll
        for (int off = 16; off > 0; off >>= 1) p += __shfl_xor_sync(0xffffffffu, p, off);
        sc[n] = p;
    }
    if (lane == 0) {
        int i0 = 0;
        for (int n = 1; n < NC; n++) if (sc[n] > sc[i0]) i0 = n;
        int i1 = -1;
        for (int n = 0; n < NC; n++) {
            if (n == i0) continue;
            if (i1 < 0 || sc[n] > sc[i1]) i1 = n;
        }
        idx[h * 2 + 0] = min(i0, i1);
        idx[h * 2 + 1] = max(i0, i1);
    }
}

// ======================================================================
// Flash attention (fp32 FFMA): per (q-tile 128, head).
// ======================================================================
#define SMEM_FLASH (3 * 128 * 132 * 4)

__device__ __forceinline__ void flash_tile_body(
    float* __restrict__ Qt, float* __restrict__ KP, float* __restrict__ Vs,
    const float* __restrict__ k, const float* __restrict__ v,
    int kb, int c0, int c1, int tx, int ty, int d0,
    float (&accO)[8][8], float (&m_i)[8], float (&l_i)[8], bool masked)
{
    const float scl = 0.08838834764831843f;  // 1/sqrt(128)
    __syncthreads();  // protect prev-iter P/V reads
#pragma unroll
    for (int p = 0; p < 8; p++) {
        int c = p * 16 + ty;
        int jg = kb + c;
        float4 kv0 = make_float4(0.f,0.f,0.f,0.f), kv1 = kv0, vv0 = kv0, vv1 = kv0;
        if (!masked || jg < LSEL) {
            int src = (jg < CHK) ? (c0 + jg) : (c1 + jg - CHK);
            const float* kp_ = k + (size_t)src * DIMM + d0;
            kv0 = *(const float4*)kp_;
            kv1 = *(const float4*)(kp_ + 4);
            const float* vp_ = v + (size_t)src * DIMM + d0;
            vv0 = *(const float4*)vp_;
            vv1 = *(const float4*)(vp_ + 4);
        }
        KP[(d0 + 0) * 132 + c] = kv0.x; KP[(d0 + 1) * 132 + c] = kv0.y;
        KP[(d0 + 2) * 132 + c] = kv0.z; KP[(d0 + 3) * 132 + c] = kv0.w;
        KP[(d0 + 4) * 132 + c] = kv1.x; KP[(d0 + 5) * 132 + c] = kv1.y;
        KP[(d0 + 6) * 132 + c] = kv1.z; KP[(d0 + 7) * 132 + c] = kv1.w;
        *(float4*)&Vs[c * 132 + d0]     = vv0;
        *(float4*)&Vs[c * 132 + d0 + 4] = vv1;
    }
    __syncthreads();

    float s8[8][8];
#pragma unroll
    for (int i = 0; i < 8; i++)
#pragma unroll
        for (int j = 0; j < 8; j++) s8[i][j] = 0.f;
#pragma unroll 8
    for (int kk = 0; kk < 128; kk++) {
        float a[8], b[8];
        float4 tt;
        tt = *(const float4*)&Qt[kk * 132 + ty * 8];     a[0]=tt.x; a[1]=tt.y; a[2]=tt.z; a[3]=tt.w;
        tt = *(const float4*)&Qt[kk * 132 + ty * 8 + 4]; a[4]=tt.x; a[5]=tt.y; a[6]=tt.z; a[7]=tt.w;
        tt = *(const float4*)&KP[kk * 132 + tx * 8];     b[0]=tt.x; b[1]=tt.y; b[2]=tt.z; b[3]=tt.w;
        tt = *(const float4*)&KP[kk * 132 + tx * 8 + 4]; b[4]=tt.x; b[5]=tt.y; b[6]=tt.z; b[7]=tt.w;
#pragma unroll
        for (int i = 0; i < 8; i++)
#pragma unroll
            for (int j = 0; j < 8; j++)
                s8[i][j] += a[i] * b[j];
    }

    float mt[8];
#pragma unroll
    for (int i = 0; i < 8; i++) {
        float mx = -1e30f;
#pragma unroll
        for (int j = 0; j < 8; j++) {
            float val = s8[i][j] * scl;
            if (masked && (kb + tx * 8 + j >= LSEL)) val = -1e30f;
            s8[i][j] = val;
            mx = fmaxf(mx, val);
        }
#pragma unroll
        for (int off = 1; off < 16; off <<= 1)
            mx = fmaxf(mx, __shfl_xor_sync(0xffffffffu, mx, off));
        mt[i] = mx;
    }
#pragma unroll
    for (int i = 0; i < 8; i++) {
        float mn = fmaxf(m_i[i], mt[i]);
        float alpha = __expf(m_i[i] - mn);
        m_i[i] = mn;
        float r = 0.f;
#pragma unroll
        for (int j = 0; j < 8; j++) {
            float p_ = __expf(s8[i][j] - mn);
            s8[i][j] = p_;
            r += p_;
        }
#pragma unroll
        for (int off = 1; off < 16; off <<= 1)
            r += __shfl_xor_sync(0xffffffffu, r, off);
        l_i[i] = l_i[i] * alpha + r;
#pragma unroll
        for (int j = 0; j < 8; j++) accO[i][j] *= alpha;
    }

    __syncthreads();
#pragma unroll
    for (int i = 0; i < 8; i++) {
#pragma unroll
        for (int j = 0; j < 8; j++)
            KP[(ty * 8 + i) * 132 + tx * 8 + j] = s8[i][j];
    }
    __syncthreads();

#pragma unroll 8
    for (int kk = 0; kk < 128; kk++) {
        float a[8], b[8];
#pragma unroll
        for (int i = 0; i < 8; i++) a[i] = KP[(ty * 8 + i) * 132 + kk];
        float4 tt;
        tt = *(const float4*)&Vs[kk * 132 + tx * 8];     b[0]=tt.x; b[1]=tt.y; b[2]=tt.z; b[3]=tt.w;
        tt = *(const float4*)&Vs[kk * 132 + tx * 8 + 4]; b[4]=tt.x; b[5]=tt.y; b[6]=tt.z; b[7]=tt.w;
#pragma unroll
        for (int i = 0; i < 8; i++)
#pragma unroll
            for (int j = 0; j < 8; j++)
                accO[i][j] += a[i] * b[j];
    }
}

__global__ __launch_bounds__(256, 1) void flash_kernel(
    const float* __restrict__ q, const float* __restrict__ k,
    const float* __restrict__ v, const int* __restrict__ idx,
    float* __restrict__ o)
{
    extern __shared__ float sm[];
    float* Qt = sm;
    float* KP = sm + 128 * 132;
    float* Vs = sm + 2 * 128 * 132;

    const int h  = blockIdx.y;
    const int q0 = blockIdx.x * 128;
    const int tid = threadIdx.x;
    const int tx = tid & 15;
    const int ty = tid >> 4;
    const int d0 = tx * 8;
    const bool qfull = (q0 + 128 <= S_TOK);

#pragma unroll
    for (int p = 0; p < 8; p++) {
        int r = p * 16 + ty;
        int gr = q0 + r;
        float4 v0 = make_float4(0.f,0.f,0.f,0.f), v1 = v0;
        if (qfull || gr < S_TOK) {
            const float* src = q + (size_t)gr * DIMM + h * HD + d0;
            v0 = *(const float4*)src;
            v1 = *(const float4*)(src + 4);
        }
        Qt[(d0 + 0) * 132 + r] = v0.x; Qt[(d0 + 1) * 132 + r] = v0.y;
        Qt[(d0 + 2) * 132 + r] = v0.z; Qt[(d0 + 3) * 132 + r] = v0.w;
        Qt[(d0 + 4) * 132 + r] = v1.x; Qt[(d0 + 5) * 132 + r] = v1.y;
        Qt[(d0 + 6) * 132 + r] = v1.z; Qt[(d0 + 7) * 132 + r] = v1.w;
    }
    const int c0 = idx[h * 2 + 0] * CHK;
    const int c1 = idx[h * 2 + 1] * CHK;
    const float* kh = k + h * HD;
    const float* vh = v + h * HD;

    float accO[8][8];
    float m_i[8], l_i[8];
#pragma unroll
    for (int i = 0; i < 8; i++) {
        m_i[i] = -1e30f; l_i[i] = 0.f;
#pragma unroll
        for (int j = 0; j < 8; j++) accO[i][j] = 0.f;
    }

    for (int t = 0; t < NKT - 1; ++t)
        flash_tile_body(Qt, KP, Vs, kh, vh, t * 128, c0, c1, tx, ty, d0,
                        accO, m_i, l_i, false);
    flash_tile_body(Qt, KP, Vs, kh, vh, (NKT - 1) * 128, c0, c1, tx, ty, d0,
                    accO, m_i, l_i, true);

#pragma unroll
    for (int i = 0; i < 8; i++) {
        int row = q0 + ty * 8 + i;
        if (!qfull && row >= S_TOK) continue;
        float inv = 1.0f / l_i[i];
        float4 o0, o1;
        o0.x = accO[i][0] * inv; o0.y = accO[i][1] * inv;
        o0.z = accO[i][2] * inv; o0.w = accO[i][3] * inv;
        o1.x = accO[i][4] * inv; o1.y = accO[i][5] * inv;
        o1.z = accO[i][6] * inv; o1.w = accO[i][7] * inv;
        float* dst = o + (size_t)row * DIMM + h * HD + tx * 8;
        *(float4*)dst = o0;
        *(float4*)(dst + 4) = o1;
    }
}

// ======================================================================
extern "C" void kernel_launch(void* const* d_in, const int* in_sizes, int n_in,
                              void* d_out, int out_size)
{
    const float* x     = (const float*)d_in[0];
    const float* freqs = (const float*)d_in[3];
    const float* wq    = (const float*)d_in[4];
    const float* bq    = (const float*)d_in[5];
    const float* wk    = (const float*)d_in[6];
    const float* bk    = (const float*)d_in[7];
    const float* wv    = (const float*)d_in[8];
    const float* bv    = (const float*)d_in[9];
    const float* wo    = (const float*)d_in[10];
    const float* bo    = (const float*)d_in[11];
    const float* gq    = (const float*)d_in[12];
    const float* gk    = (const float*)d_in[13];
    float* out = (float*)d_out;

    float *qb, *kb, *vb, *ob, *phiq, *phik;
    int* idxp;
    cudaGetSymbolAddress((void**)&qb,   g_q);
    cudaGetSymbolAddress((void**)&kb,   g_k);
    cudaGetSymbolAddress((void**)&vb,   g_v);
    cudaGetSymbolAddress((void**)&ob,   g_o);
    cudaGetSymbolAddress((void**)&phiq, g_phiq);
    cudaGetSymbolAddress((void**)&phik, g_phik);
    cudaGetSymbolAddress((void**)&idxp, g_idx);

    cudaFuncSetAttribute(gemm_mma_kernel, cudaFuncAttributeMaxDynamicSharedMemorySize, MM_SMEM);
    cudaFuncSetAttribute(flash_kernel, cudaFuncAttributeMaxDynamicSharedMemorySize, SMEM_FLASH);

    dim3 gemm_grid(DIMM / 128, (S_TOK + 127) / 128);
    gemm_mma_kernel<<<gemm_grid, 256, MM_SMEM>>>(x, wq, bq, qb, S_TOK);
    gemm_mma_kernel<<<gemm_grid, 256, MM_SMEM>>>(x, wk, bk, kb, S_TOK);
    gemm_mma_kernel<<<gemm_grid, 256, MM_SMEM>>>(x, wv, bv, vb, S_TOK);

    norm_rope_kernel<<<dim3(S_TOK, 2), 256>>>(qb, kb, gq, gk, freqs);

    phi_kernel<<<NC * NH + NH, 128>>>(qb, kb, phiq, phik);
    route_kernel<<<NH, 32>>>(phiq, phik, idxp);

    flash_kernel<<<dim3((S_TOK + 127) / 128, NH), 256, SMEM_FLASH>>>(qb, kb, vb, idxp, ob);

    gemm_mma_kernel<<<gemm_grid, 256, MM_SMEM>>>(ob, wo, bo, out, S_TOK);
}

// round 9
// speedup vs baseline: 1.7888x; 1.4383x over previous
#include <cuda_runtime.h>
#include <cuda_bf16.h>
#include <math.h>
#include <stdint.h>

// ---------------- problem constants (fixed shapes) ----------------
#define S_TOK 6240
#define DIMM  1536
#define NH    12
#define HD    128
#define CHK   1560          // chunk = 30*52 (divisible by 8)
#define NC    4             // number of chunks
#define LSEL  3120          // top_k(2) * CHK (divisible by 8)
#define NKT   25            // ceil(3120/128); last tile has 48 valid keys
#define C1    22            // rope split: 64 - 2*(64/3)
#define C2    21

// ---------------- scratch (device globals: no cudaMalloc allowed) ----------------
__device__ float g_q[(size_t)S_TOK * DIMM];
__device__ float g_k[(size_t)S_TOK * DIMM];
__device__ float g_v[(size_t)S_TOK * DIMM];
__device__ float g_o[(size_t)S_TOK * DIMM];
__device__ float g_phiq[NH * HD];
__device__ float g_phik[NC * NH * HD];
__device__ int   g_idx[NH * 2];
// bf16 hi/lo copies for HMMA flash
__device__ __nv_bfloat16 g_qh[(size_t)S_TOK * DIMM];
__device__ __nv_bfloat16 g_ql[(size_t)S_TOK * DIMM];
__device__ __nv_bfloat16 g_kh[(size_t)S_TOK * DIMM];
__device__ __nv_bfloat16 g_kl[(size_t)S_TOK * DIMM];
__device__ __nv_bfloat16 g_vth[(size_t)DIMM * S_TOK];  // [dim][seq]
__device__ __nv_bfloat16 g_vtl[(size_t)DIMM * S_TOK];

// ======================================================================
// warp-mma helpers (base sm_100: ldmatrix + mma.sync)
// ======================================================================
__device__ __forceinline__ uint32_t smem_u32(const void* p) {
    uint32_t a;
    asm("{ .reg .u64 t; cvta.to.shared.u64 t, %1; cvt.u32.u64 %0, t; }" : "=r"(a) : "l"(p));
    return a;
}
__device__ __forceinline__ void ldm_x4(uint32_t* r, uint32_t addr) {
    asm volatile("ldmatrix.sync.aligned.m8n8.x4.shared.b16 {%0,%1,%2,%3}, [%4];"
        : "=r"(r[0]), "=r"(r[1]), "=r"(r[2]), "=r"(r[3]) : "r"(addr));
}
__device__ __forceinline__ void ldm_x2(uint32_t* r, uint32_t addr) {
    asm volatile("ldmatrix.sync.aligned.m8n8.x2.shared.b16 {%0,%1}, [%2];"
        : "=r"(r[0]), "=r"(r[1]) : "r"(addr));
}
__device__ __forceinline__ void mma16816(float* c, const uint32_t* a, const uint32_t* b) {
    asm volatile("mma.sync.aligned.m16n8k16.row.col.f32.bf16.bf16.f32 "
        "{%0,%1,%2,%3}, {%4,%5,%6,%7}, {%8,%9}, {%0,%1,%2,%3};"
        : "+f"(c[0]), "+f"(c[1]), "+f"(c[2]), "+f"(c[3])
        : "r"(a[0]), "r"(a[1]), "r"(a[2]), "r"(a[3]), "r"(b[0]), "r"(b[1]));
}

__device__ __forceinline__ uint32_t pack_bf2(__nv_bfloat16 a, __nv_bfloat16 b) {
    return ((uint32_t)__bfloat16_as_ushort(b) << 16) | (uint32_t)__bfloat16_as_ushort(a);
}
__device__ __forceinline__ void split8(const float4 f0, const float4 f1,
                                       uint4& hi, uint4& lo) {
    float x[8] = {f0.x, f0.y, f0.z, f0.w, f1.x, f1.y, f1.z, f1.w};
    __nv_bfloat16 h[8], l[8];
#pragma unroll
    for (int i = 0; i < 8; i++) {
        h[i] = __float2bfloat16(x[i]);
        l[i] = __float2bfloat16(x[i] - __bfloat162float(h[i]));
    }
    hi.x = pack_bf2(h[0], h[1]); hi.y = pack_bf2(h[2], h[3]);
    hi.z = pack_bf2(h[4], h[5]); hi.w = pack_bf2(h[6], h[7]);
    lo.x = pack_bf2(l[0], l[1]); lo.y = pack_bf2(l[2], l[3]);
    lo.z = pack_bf2(l[4], l[5]); lo.w = pack_bf2(l[6], l[7]);
}
__device__ __forceinline__ void split2(float a, float b, uint32_t& hi, uint32_t& lo) {
    __nv_bfloat16 ha = __float2bfloat16(a), hb = __float2bfloat16(b);
    __nv_bfloat16 la = __float2bfloat16(a - __bfloat162float(ha));
    __nv_bfloat16 lb = __float2bfloat16(b - __bfloat162float(hb));
    hi = pack_bf2(ha, hb); lo = pack_bf2(la, lb);
}

// ======================================================================
// HMMA GEMM (validated round 7): C = A @ W^T + bias
// ======================================================================
#define KC 32
#define NCHUNK (DIMM / KC)          // 48
#define RSG 40                      // gemm smem row stride, bf16
#define ARR_B (128 * RSG * 2)       // 10240 B
#define STAGE_B (4 * ARR_B)
#define MM_SMEM (2 * STAGE_B)       // 81920 B

__global__ __launch_bounds__(256, 1)
void gemm_mma_kernel(const float* __restrict__ A, const float* __restrict__ W,
                     const float* __restrict__ bias, float* __restrict__ C, int M)
{
    extern __shared__ char sm_raw[];
    const uint32_t sb = smem_u32(sm_raw);
    const int tid  = threadIdx.x;
    const int lane = tid & 31;
    const int warp = tid >> 5;
    const int wm = warp >> 2;
    const int wn = warp & 3;
    const int bm = blockIdx.y * 128;
    const int bn = blockIdx.x * 128;
    const bool full = (bm + 128 <= M);

    const int lrow = tid >> 1;
    const int lcb  = (tid & 1) * 16;
    const bool arow_ok = full || (bm + lrow < M);
    const int arow_clamped = arow_ok ? (bm + lrow) : 0;
    const float* arow_p = A + (size_t)arow_clamped * DIMM + lcb;
    const float* wrow_p = W + (size_t)(bn + lrow) * DIMM + lcb;

    float4 pa[4], pw[4];
    float acc[4][4][4];
#pragma unroll
    for (int mi = 0; mi < 4; mi++)
#pragma unroll
        for (int ni = 0; ni < 4; ni++)
#pragma unroll
            for (int e = 0; e < 4; e++) acc[mi][ni][e] = 0.f;

    {
        if (arow_ok) {
            const float4* p = (const float4*)arow_p;
            pa[0] = p[0]; pa[1] = p[1]; pa[2] = p[2]; pa[3] = p[3];
        } else {
            pa[0] = pa[1] = pa[2] = pa[3] = make_float4(0.f, 0.f, 0.f, 0.f);
        }
        const float4* q = (const float4*)wrow_p;
        pw[0] = q[0]; pw[1] = q[1]; pw[2] = q[2]; pw[3] = q[3];

        char* base = sm_raw;
        const uint32_t off = (uint32_t)(lrow * RSG + lcb) * 2;
        uint4 hi, lo;
        split8(pa[0], pa[1], hi, lo);
        *(uint4*)(base + off) = hi;  *(uint4*)(base + ARR_B + off) = lo;
        split8(pa[2], pa[3], hi, lo);
        *(uint4*)(base + off + 16) = hi;  *(uint4*)(base + ARR_B + off + 16) = lo;
        split8(pw[0], pw[1], hi, lo);
        *(uint4*)(base + 2 * ARR_B + off) = hi;  *(uint4*)(base + 3 * ARR_B + off) = lo;
        split8(pw[2], pw[3], hi, lo);
        *(uint4*)(base + 2 * ARR_B + off + 16) = hi;  *(uint4*)(base + 3 * ARR_B + off + 16) = lo;
    }
    __syncthreads();

    const uint32_t aoff = (uint32_t)((lane & 15) * RSG + ((lane >> 4) << 3)) * 2;
    const uint32_t boff = (uint32_t)((lane & 7) * RSG + (((lane >> 3) & 1) << 3)) * 2;

    for (int c = 0; c < NCHUNK; ++c) {
        const int buf = c & 1;
        if (c + 1 < NCHUNK) {
            const int k0 = (c + 1) * KC;
            if (arow_ok) {
                const float4* p = (const float4*)(arow_p + k0);
                pa[0] = p[0]; pa[1] = p[1]; pa[2] = p[2]; pa[3] = p[3];
            } else {
                pa[0] = pa[1] = pa[2] = pa[3] = make_float4(0.f, 0.f, 0.f, 0.f);
            }
            const float4* q = (const float4*)(wrow_p + k0);
            pw[0] = q[0]; pw[1] = q[1]; pw[2] = q[2]; pw[3] = q[3];
        }

        const uint32_t st = sb + buf * STAGE_B;
#pragma unroll
        for (int ks = 0; ks < 2; ++ks) {
            uint32_t ahi[4][4], alo[4][4], bhi[4][2], blo[4][2];
            const uint32_t kso = ks * 32;
#pragma unroll
            for (int mi = 0; mi < 4; ++mi) {
                uint32_t r = st + (uint32_t)((wm * 64 + mi * 16) * RSG * 2) + aoff + kso;
                ldm_x4(ahi[mi], r);
                ldm_x4(alo[mi], r + ARR_B);
            }
#pragma unroll
            for (int ni = 0; ni < 4; ++ni) {
                uint32_t r = st + 2 * ARR_B + (uint32_t)((wn * 32 + ni * 8) * RSG * 2) + boff + kso;
                ldm_x2(bhi[ni], r);
                ldm_x2(blo[ni], r + ARR_B);
            }
#pragma unroll
            for (int mi = 0; mi < 4; ++mi)
#pragma unroll
                for (int ni = 0; ni < 4; ++ni) {
                    mma16816(acc[mi][ni], ahi[mi], bhi[ni]);
                    mma16816(acc[mi][ni], ahi[mi], blo[ni]);
                    mma16816(acc[mi][ni], alo[mi], bhi[ni]);
                }
        }

        if (c + 1 < NCHUNK) {
            __syncthreads();
            char* base = sm_raw + (buf ^ 1) * STAGE_B;
            const uint32_t off = (uint32_t)(lrow * RSG + lcb) * 2;
            uint4 hi, lo;
            split8(pa[0], pa[1], hi, lo);
            *(uint4*)(base + off) = hi;  *(uint4*)(base + ARR_B + off) = lo;
            split8(pa[2], pa[3], hi, lo);
            *(uint4*)(base + off + 16) = hi;  *(uint4*)(base + ARR_B + off + 16) = lo;
            split8(pw[0], pw[1], hi, lo);
            *(uint4*)(base + 2 * ARR_B + off) = hi;  *(uint4*)(base + 3 * ARR_B + off) = lo;
            split8(pw[2], pw[3], hi, lo);
            *(uint4*)(base + 2 * ARR_B + off + 16) = hi;  *(uint4*)(base + 3 * ARR_B + off + 16) = lo;
            __syncthreads();
        }
    }

#pragma unroll
    for (int mi = 0; mi < 4; ++mi) {
        const int r0 = bm + wm * 64 + mi * 16 + (lane >> 2);
#pragma unroll
        for (int ni = 0; ni < 4; ++ni) {
            const int c0 = bn + wn * 32 + ni * 8 + (lane & 3) * 2;
            const float b0 = bias[c0], b1 = bias[c0 + 1];
            if (full || r0 < M) {
                float2 v = make_float2(acc[mi][ni][0] + b0, acc[mi][ni][1] + b1);
                *(float2*)(C + (size_t)r0 * DIMM + c0) = v;
            }
            if (full || r0 + 8 < M) {
                float2 v = make_float2(acc[mi][ni][2] + b0, acc[mi][ni][3] + b1);
                *(float2*)(C + (size_t)(r0 + 8) * DIMM + c0) = v;
            }
        }
    }
}

// ======================================================================
// Fused RMSNorm + 3D RoPE (unchanged)
// ======================================================================
__global__ __launch_bounds__(256) void norm_rope_kernel(
    float* __restrict__ q, float* __restrict__ k,
    const float* __restrict__ gq, const float* __restrict__ gk,
    const float* __restrict__ freqs)
{
    const int s = blockIdx.x;
    float* row = (blockIdx.y == 0 ? q : k) + (size_t)s * DIMM;
    const float* g = (blockIdx.y == 0 ? gq : gk);
    const int tid = threadIdx.x;

    float ss = 0.f;
#pragma unroll
    for (int i = 0; i < 6; i++) { float v = row[tid + i * 256]; ss += v * v; }
#pragma unroll
    for (int off = 16; off > 0; off >>= 1) ss += __shfl_xor_sync(0xffffffffu, ss, off);
    __shared__ float warp_s[8];
    __shared__ float total_s;
    if ((tid & 31) == 0) warp_s[tid >> 5] = ss;
    __syncthreads();
    if (tid == 0) {
        float t = 0.f;
#pragma unroll
        for (int i = 0; i < 8; i++) t += warp_s[i];
        total_s = t;
    }
    __syncthreads();
    const float scale = rsqrtf(total_s * (1.0f / DIMM) + 1e-6f);

    const int f  = s / CHK;
    const int rm = s % CHK;
    const int hh = rm / 52;
    const int ww = rm % 52;

    for (int p = tid; p < DIMM / 2; p += 256) {
        int d0 = 2 * p;
        float a = row[d0]     * scale * g[d0];
        float b = row[d0 + 1] * scale * g[d0 + 1];
        int jh = p & 63;
        int pos = (jh < C1) ? f : ((jh < C1 + C2) ? hh : ww);
        float cv = freqs[(pos * 64 + jh) * 2 + 0];
        float sv = freqs[(pos * 64 + jh) * 2 + 1];
        row[d0]     = a * cv - b * sv;
        row[d0 + 1] = a * sv + b * cv;
    }
}

// ======================================================================
// convert q,k (fp32, post-rope) -> bf16 hi/lo arrays. grid.y: 0=q, 1=k
// ======================================================================
__global__ __launch_bounds__(256) void qk_convert_kernel(
    const float* __restrict__ q, const float* __restrict__ k,
    __nv_bfloat16* __restrict__ qh, __nv_bfloat16* __restrict__ ql,
    __nv_bfloat16* __restrict__ kh, __nv_bfloat16* __restrict__ kl)
{
    const size_t i = (size_t)blockIdx.x * 256 + threadIdx.x;   // float4 index
    const float* src = blockIdx.y == 0 ? q : k;
    __nv_bfloat16* dh = blockIdx.y == 0 ? qh : kh;
    __nv_bfloat16* dl = blockIdx.y == 0 ? ql : kl;
    float4 v = ((const float4*)src)[i];
    __nv_bfloat16 h0 = __float2bfloat16(v.x), h1 = __float2bfloat16(v.y);
    __nv_bfloat16 h2 = __float2bfloat16(v.z), h3 = __float2bfloat16(v.w);
    uint2 ho, lo;
    ho.x = pack_bf2(h0, h1); ho.y = pack_bf2(h2, h3);
    lo.x = pack_bf2(__float2bfloat16(v.x - __bfloat162float(h0)),
                    __float2bfloat16(v.y - __bfloat162float(h1)));
    lo.y = pack_bf2(__float2bfloat16(v.z - __bfloat162float(h2)),
                    __float2bfloat16(v.w - __bfloat162float(h3)));
    ((uint2*)dh)[i] = ho;
    ((uint2*)dl)[i] = lo;
}

// ======================================================================
// transpose + convert V: [s][dim] fp32 -> [dim][s] bf16 hi/lo
// block (32,8); tile 32x32; grid (195, 48)
// ======================================================================
__global__ __launch_bounds__(256) void v_transpose_kernel(
    const float* __restrict__ v,
    __nv_bfloat16* __restrict__ vth, __nv_bfloat16* __restrict__ vtl)
{
    __shared__ float tile[32][33];
    const int s0 = blockIdx.x * 32;
    const int d0 = blockIdx.y * 32;
    const int tx = threadIdx.x, ty = threadIdx.y;
#pragma unroll
    for (int yy = 0; yy < 4; ++yy) {
        int s = s0 + ty + yy * 8;
        tile[ty + yy * 8][tx] = v[(size_t)s * DIMM + d0 + tx];
    }
    __syncthreads();
#pragma unroll
    for (int yy = 0; yy < 4; ++yy) {
        int d = d0 + ty + yy * 8;
        int s = s0 + tx;
        float x = tile[tx][ty + yy * 8];
        __nv_bfloat16 h = __float2bfloat16(x);
        vth[(size_t)d * S_TOK + s] = h;
        vtl[(size_t)d * S_TOK + s] = __float2bfloat16(x - __bfloat162float(h));
    }
}

// ======================================================================
// phi / route (unchanged)
// ======================================================================
__global__ void phi_kernel(const float* __restrict__ q, const float* __restrict__ k,
                           float* __restrict__ phiq, float* __restrict__ phik)
{
    int d = threadIdx.x;
    int b = blockIdx.x;
    if (b < NC * NH) {
        int n = b / NH, h = b % NH;
        float sum = 0.f;
        const float* base = k + (size_t)(n * CHK) * DIMM + h * HD + d;
        for (int r = 0; r < CHK; r++) sum += base[(size_t)r * DIMM];
        phik[(n * NH + h) * HD + d] = sum * (1.0f / CHK);
    } else {
        int h = b - NC * NH;
        float sum = 0.f;
        const float* base = q + h * HD + d;
        for (int r = 0; r < S_TOK; r++) sum += base[(size_t)r * DIMM];
        phiq[h * HD + d] = sum * (1.0f / S_TOK);
    }
}

__global__ void route_kernel(const float* __restrict__ phiq,
                             const float* __restrict__ phik, int* __restrict__ idx)
{
    int h = blockIdx.x;
    int lane = threadIdx.x;
    float sc[NC];
#pragma unroll
    for (int n = 0; n < NC; n++) {
        float p = 0.f;
        for (int d = lane; d < HD; d += 32)
            p += phiq[h * HD + d] * phik[(n * NH + h) * HD + d];
#pragma unroll
        for (int off = 16; off > 0; off >>= 1) p += __shfl_xor_sync(0xffffffffu, p, off);
        sc[n] = p;
    }
    if (lane == 0) {
        int i0 = 0;
        for (int n = 1; n < NC; n++) if (sc[n] > sc[i0]) i0 = n;
        int i1 = -1;
        for (int n = 0; n < NC; n++) {
            if (n == i0) continue;
            if (i1 < 0 || sc[n] > sc[i1]) i1 = n;
        }
        idx[h * 2 + 0] = min(i0, i1);
        idx[h * 2 + 1] = max(i0, i1);
    }
}

// ======================================================================
// HMMA flash attention.
// 8 warps x 16 q-rows; full 128-key / 128-d span per warp.
// smem arrays (row stride 136 bf16 = 272B, conflict-free ldmatrix):
//   QH QL [qrow][d]   KH KL [key][d]   VH VL [d][key]
// ======================================================================
#define RSF 136
#define AELT (128 * RSF)            // elements per array
#define ABYT (AELT * 2)             // 34816 B
#define FL_SMEM (6 * ABYT)          // 208896 B

__global__ __launch_bounds__(256, 1) void flash_mma_kernel(
    const __nv_bfloat16* __restrict__ qh, const __nv_bfloat16* __restrict__ ql,
    const __nv_bfloat16* __restrict__ kh, const __nv_bfloat16* __restrict__ kl,
    const __nv_bfloat16* __restrict__ vth, const __nv_bfloat16* __restrict__ vtl,
    const int* __restrict__ idx, float* __restrict__ o)
{
    extern __shared__ char sm_raw[];
    const uint32_t sb = smem_u32(sm_raw);
    const uint32_t sQH = sb, sKH = sb + 2 * ABYT, sVH = sb + 4 * ABYT;
    const int h  = blockIdx.y;
    const int q0 = blockIdx.x * 128;
    const int tid = threadIdx.x;
    const int lane = tid & 31;
    const int warp = tid >> 5;

    const int lrow = tid >> 1;         // 0..127
    const int half = tid & 1;          // 64-element halves

    // ---- load Q tile (hi/lo) ----
    {
        int gr = q0 + lrow;
        bool ok = gr < S_TOK;
        size_t src = (size_t)(ok ? gr : 0) * DIMM + h * HD + half * 64;
        char* d0p = sm_raw + (size_t)(lrow * RSF + half * 64) * 2;
        const uint4* ph = (const uint4*)(qh + src);
        const uint4* pl = (const uint4*)(ql + src);
        uint4 z = make_uint4(0, 0, 0, 0);
#pragma unroll
        for (int i = 0; i < 8; i++) {
            *(uint4*)(d0p + i * 16)        = ok ? ph[i] : z;
            *(uint4*)(d0p + ABYT + i * 16) = ok ? pl[i] : z;
        }
    }
    const int c0 = idx[h * 2 + 0] * CHK;
    const int c1 = idx[h * 2 + 1] * CHK;

    float accO[16][4];
    float m0 = -1e30f, m1 = -1e30f, l0 = 0.f, l1 = 0.f;
#pragma unroll
    for (int dt = 0; dt < 16; dt++)
#pragma unroll
        for (int e = 0; e < 4; e++) accO[dt][e] = 0.f;

    const float scl = 0.08838834764831843f;   // 1/sqrt(128)
    const uint32_t aoff = (uint32_t)((lane & 15) * RSF + ((lane >> 4) << 3)) * 2
                        + (uint32_t)(warp * 16 * RSF) * 2;
    const uint32_t boff = (uint32_t)((lane & 7) * RSF + (((lane >> 3) & 1) << 3)) * 2;

    for (int t = 0; t < NKT; ++t) {
        const int kb = t * 128;
        const bool masked = (t == NKT - 1);
        __syncthreads();   // previous-iter reads done

        // ---- load K tile [key][d] hi/lo ----
        {
            int jg = kb + lrow;
            bool ok = !masked || (jg < LSEL);
            int src = (jg < CHK) ? (c0 + jg) : (c1 + jg - CHK);
            if (!ok) src = 0;
            size_t so = (size_t)src * DIMM + h * HD + half * 64;
            char* dp = sm_raw + 2 * (size_t)ABYT + (size_t)(lrow * RSF + half * 64) * 2;
            const uint4* ph = (const uint4*)(kh + so);
            const uint4* pl = (const uint4*)(kl + so);
            uint4 z = make_uint4(0, 0, 0, 0);
#pragma unroll
            for (int i = 0; i < 8; i++) {
                *(uint4*)(dp + i * 16)        = ok ? ph[i] : z;
                *(uint4*)(dp + ABYT + i * 16) = ok ? pl[i] : z;
            }
        }
        // ---- load V tile [d][key] hi/lo (key groups of 8 never straddle chunks) ----
        {
            int d = lrow;
            char* dp = sm_raw + 4 * (size_t)ABYT + (size_t)(d * RSF + half * 64) * 2;
            const size_t rowbase = (size_t)(h * HD + d) * S_TOK;
            uint4 z = make_uint4(0, 0, 0, 0);
#pragma unroll
            for (int g = 0; g < 8; g++) {
                int kg = kb + half * 64 + g * 8;
                bool ok = !masked || (kg < LSEL);
                int src = (kg < CHK) ? (c0 + kg) : (c1 + kg - CHK);
                if (!ok) src = 0;
                *(uint4*)(dp + g * 16)        = ok ? *(const uint4*)(vth + rowbase + src) : z;
                *(uint4*)(dp + ABYT + g * 16) = ok ? *(const uint4*)(vtl + rowbase + src) : z;
            }
        }
        __syncthreads();

        // ---- S = Q K^T (split 3-pass) ----
        float s8[16][4];
#pragma unroll
        for (int nt = 0; nt < 16; nt++)
#pragma unroll
            for (int e = 0; e < 4; e++) s8[nt][e] = 0.f;
#pragma unroll
        for (int ks = 0; ks < 8; ++ks) {
            uint32_t ah[4], al[4];
            uint32_t qa = sQH + aoff + ks * 32;
            ldm_x4(ah, qa);
            ldm_x4(al, qa + ABYT);
#pragma unroll
            for (int nt = 0; nt < 16; ++nt) {
                uint32_t bh[2], bl[2];
                uint32_t ka = sKH + (uint32_t)(nt * 8 * RSF) * 2 + boff + ks * 32;
                ldm_x2(bh, ka);
                ldm_x2(bl, ka + ABYT);
                mma16816(s8[nt], ah, bh);
                mma16816(s8[nt], ah, bl);
                mma16816(s8[nt], al, bh);
            }
        }

        // ---- online softmax (rows fully within warp; 4-lane reductions) ----
        const int ntv = masked ? 6 : 16;   // valid-key count is 48 = 6 n-tiles on last tile
        float mx0 = -1e30f, mx1 = -1e30f;
#pragma unroll
        for (int nt = 0; nt < 16; nt++) {
            if (nt >= ntv) break;
#pragma unroll
            for (int e = 0; e < 4; e++) s8[nt][e] *= scl;
            mx0 = fmaxf(mx0, fmaxf(s8[nt][0], s8[nt][1]));
            mx1 = fmaxf(mx1, fmaxf(s8[nt][2], s8[nt][3]));
        }
        mx0 = fmaxf(mx0, __shfl_xor_sync(0xffffffffu, mx0, 1));
        mx0 = fmaxf(mx0, __shfl_xor_sync(0xffffffffu, mx0, 2));
        mx1 = fmaxf(mx1, __shfl_xor_sync(0xffffffffu, mx1, 1));
        mx1 = fmaxf(mx1, __shfl_xor_sync(0xffffffffu, mx1, 2));
        float mn0 = fmaxf(m0, mx0), mn1 = fmaxf(m1, mx1);
        float al0 = __expf(m0 - mn0), al1 = __expf(m1 - mn1);
        m0 = mn0; m1 = mn1;
        float sum0 = 0.f, sum1 = 0.f;
#pragma unroll
        for (int nt = 0; nt < 16; nt++) {
            if (nt < ntv) {
                float p0 = __expf(s8[nt][0] - mn0);
                float p1 = __expf(s8[nt][1] - mn0);
                float p2 = __expf(s8[nt][2] - mn1);
                float p3 = __expf(s8[nt][3] - mn1);
                s8[nt][0] = p0; s8[nt][1] = p1; s8[nt][2] = p2; s8[nt][3] = p3;
                sum0 += p0 + p1; sum1 += p2 + p3;
            } else {
                s8[nt][0] = s8[nt][1] = s8[nt][2] = s8[nt][3] = 0.f;
            }
        }
        sum0 += __shfl_xor_sync(0xffffffffu, sum0, 1);
        sum0 += __shfl_xor_sync(0xffffffffu, sum0, 2);
        sum1 += __shfl_xor_sync(0xffffffffu, sum1, 1);
        sum1 += __shfl_xor_sync(0xffffffffu, sum1, 2);
        l0 = l0 * al0 + sum0;
        l1 = l1 * al1 + sum1;
#pragma unroll
        for (int dt = 0; dt < 16; dt++) {
            accO[dt][0] *= al0; accO[dt][1] *= al0;
            accO[dt][2] *= al1; accO[dt][3] *= al1;
        }

        // ---- O += P V (split 3-pass; P frags from S frags) ----
#pragma unroll
        for (int j = 0; j < 8; ++j) {
            uint32_t ph[4], pl[4];
            split2(s8[2 * j][0],     s8[2 * j][1],     ph[0], pl[0]);
            split2(s8[2 * j][2],     s8[2 * j][3],     ph[1], pl[1]);
            split2(s8[2 * j + 1][0], s8[2 * j + 1][1], ph[2], pl[2]);
            split2(s8[2 * j + 1][2], s8[2 * j + 1][3], ph[3], pl[3]);
#pragma unroll
            for (int dt = 0; dt < 16; ++dt) {
                uint32_t vh[2], vl[2];
                uint32_t va = sVH + (uint32_t)(dt * 8 * RSF) * 2 + boff + j * 32;
                ldm_x2(vh, va);
                ldm_x2(vl, va + ABYT);
                mma16816(accO[dt], ph, vh);
                mma16816(accO[dt], pl, vh);
                mma16816(accO[dt], ph, vl);
            }
        }
    }

    // ---- epilogue ----
    const float inv0 = 1.0f / l0;
    const float inv1 = 1.0f / l1;
    const int row0 = q0 + warp * 16 + (lane >> 2);
    const int row1 = row0 + 8;
#pragma unroll
    for (int dt = 0; dt < 16; ++dt) {
        const int col = h * HD + dt * 8 + (lane & 3) * 2;
        if (row0 < S_TOK)
            *(float2*)(o + (size_t)row0 * DIMM + col) =
                make_float2(accO[dt][0] * inv0, accO[dt][1] * inv0);
        if (row1 < S_TOK)
            *(float2*)(o + (size_t)row1 * DIMM + col) =
                make_float2(accO[dt][2] * inv1, accO[dt][3] * inv1);
    }
}

// ======================================================================
extern "C" void kernel_launch(void* const* d_in, const int* in_sizes, int n_in,
                              void* d_out, int out_size)
{
    const float* x     = (const float*)d_in[0];
    const float* freqs = (const float*)d_in[3];
    const float* wq    = (const float*)d_in[4];
    const float* bq    = (const float*)d_in[5];
    const float* wk    = (const float*)d_in[6];
    const float* bk    = (const float*)d_in[7];
    const float* wv    = (const float*)d_in[8];
    const float* bv    = (const float*)d_in[9];
    const float* wo    = (const float*)d_in[10];
    const float* bo    = (const float*)d_in[11];
    const float* gq    = (const float*)d_in[12];
    const float* gk    = (const float*)d_in[13];
    float* out = (float*)d_out;

    float *qb, *kb, *vb, *ob, *phiq, *phik;
    int* idxp;
    __nv_bfloat16 *qh, *ql, *kh, *kl, *vth, *vtl;
    cudaGetSymbolAddress((void**)&qb,   g_q);
    cudaGetSymbolAddress((void**)&kb,   g_k);
    cudaGetSymbolAddress((void**)&vb,   g_v);
    cudaGetSymbolAddress((void**)&ob,   g_o);
    cudaGetSymbolAddress((void**)&phiq, g_phiq);
    cudaGetSymbolAddress((void**)&phik, g_phik);
    cudaGetSymbolAddress((void**)&idxp, g_idx);
    cudaGetSymbolAddress((void**)&qh,   g_qh);
    cudaGetSymbolAddress((void**)&ql,   g_ql);
    cudaGetSymbolAddress((void**)&kh,   g_kh);
    cudaGetSymbolAddress((void**)&kl,   g_kl);
    cudaGetSymbolAddress((void**)&vth,  g_vth);
    cudaGetSymbolAddress((void**)&vtl,  g_vtl);

    cudaFuncSetAttribute(gemm_mma_kernel, cudaFuncAttributeMaxDynamicSharedMemorySize, MM_SMEM);
    cudaFuncSetAttribute(flash_mma_kernel, cudaFuncAttributeMaxDynamicSharedMemorySize, FL_SMEM);

    dim3 gemm_grid(DIMM / 128, (S_TOK + 127) / 128);
    gemm_mma_kernel<<<gemm_grid, 256, MM_SMEM>>>(x, wq, bq, qb, S_TOK);
    gemm_mma_kernel<<<gemm_grid, 256, MM_SMEM>>>(x, wk, bk, kb, S_TOK);
    gemm_mma_kernel<<<gemm_grid, 256, MM_SMEM>>>(x, wv, bv, vb, S_TOK);

    norm_rope_kernel<<<dim3(S_TOK, 2), 256>>>(qb, kb, gq, gk, freqs);

    phi_kernel<<<NC * NH + NH, 128>>>(qb, kb, phiq, phik);
    route_kernel<<<NH, 32>>>(phiq, phik, idxp);

    qk_convert_kernel<<<dim3((S_TOK * DIMM / 4) / 256, 2), 256>>>(qb, kb, qh, ql, kh, kl);
    v_transpose_kernel<<<dim3(S_TOK / 32, DIMM / 32), dim3(32, 8)>>>(vb, vth, vtl);

    flash_mma_kernel<<<dim3((S_TOK + 127) / 128, NH), 256, FL_SMEM>>>(
        qh, ql, kh, kl, vth, vtl, idxp, ob);

    gemm_mma_kernel<<<gemm_grid, 256, MM_SMEM>>>(ob, wo, bo, out, S_TOK);
}